// round 10
// baseline (speedup 1.0000x reference)
#include <cuda_runtime.h>
#include <cuda_fp16.h>
#include <math.h>

#define BB 256
#define VV 50257
#define UU 65536
#define MM 3
#define NE (MM * VV)        // 150771 total (model, vocab) entries
#define NJB ((VV + 31) / 32) // 1571 j-blocks per row

// ---------------- scratch (device globals; no allocation at launch time) ----
__device__ __half g_probsT[(size_t)MM * VV * BB];  // [m][j][b], b contiguous, UNNORMALIZED exp (fp16)
__device__ float g_psum[(size_t)MM * BB * NJB];    // per-(m,b) partial sums (fp32)
__device__ float g_scale[MM * BB];                 // w_m / sum
__device__ int   g_count[UU];
__device__ int   g_off[UU + 1];
__device__ int   g_cursor[UU];
__device__ int   g_entries[NE];                    // packed pidx = m*VV + j

// ---------------- CSR inverse-map build ------------------------------------
__global__ void zero_counts() {
    int i = blockIdx.x * blockDim.x + threadIdx.x;
    if (i < UU) g_count[i] = 0;
}

__global__ void count_entries(const int* __restrict__ m0,
                              const int* __restrict__ m1,
                              const int* __restrict__ m2) {
    int idx = blockIdx.x * blockDim.x + threadIdx.x;
    if (idx >= NE) return;
    int m = idx / VV;
    int j = idx - m * VV;
    const int* mp = (m == 0) ? m0 : (m == 1) ? m1 : m2;
    atomicAdd(&g_count[mp[j]], 1);
}

// coalesced exclusive scan of 65536 counts: 1 block, 32 warps, warp-chunked
__global__ void scan_counts() {
    __shared__ int warp_tot[32];
    __shared__ int warp_pre[32];
    int t = threadIdx.x, lane = t & 31, w = t >> 5;
    const int CH = UU / 32;            // 2048 elements per warp
    int base = w * CH;

    int tot = 0;
    for (int i = lane; i < CH; i += 32) tot += g_count[base + i];
#pragma unroll
    for (int o = 16; o; o >>= 1) tot += __shfl_xor_sync(0xffffffffu, tot, o);
    if (lane == 0) warp_tot[w] = tot;
    __syncthreads();

    if (w == 0) {
        int v = warp_tot[lane];
        int s = v;
#pragma unroll
        for (int o = 1; o < 32; o <<= 1) {
            int x = __shfl_up_sync(0xffffffffu, s, o);
            if (lane >= o) s += x;
        }
        warp_pre[lane] = s - v;
        if (lane == 31) g_off[UU] = s;
    }
    __syncthreads();

    int run = warp_pre[w];
    for (int i = lane; i < CH; i += 32) {
        int v = g_count[base + i];
        int s = v;
#pragma unroll
        for (int o = 1; o < 32; o <<= 1) {
            int x = __shfl_up_sync(0xffffffffu, s, o);
            if (lane >= o) s += x;
        }
        int excl = run + s - v;
        g_off[base + i]    = excl;
        g_cursor[base + i] = excl;
        run += __shfl_sync(0xffffffffu, s, 31);
    }
}

__global__ void fill_entries(const int* __restrict__ m0,
                             const int* __restrict__ m1,
                             const int* __restrict__ m2) {
    int idx = blockIdx.x * blockDim.x + threadIdx.x;
    if (idx >= NE) return;
    int m = idx / VV;
    int j = idx - m * VV;
    const int* mp = (m == 0) ? m0 : (m == 1) ? m1 : m2;
    int u = mp[j];
    int pos = atomicAdd(&g_cursor[u], 1);
    g_entries[pos] = idx;   // pidx = m*VV + j
}

// canonicalize entry order within each bucket (determinism across replays)
__global__ void sort_buckets() {
    int u = blockIdx.x * blockDim.x + threadIdx.x;
    if (u >= UU) return;
    int s = g_off[u], e = g_off[u + 1];
    for (int i = s + 1; i < e; i++) {
        int key = g_entries[i];
        int k = i - 1;
        while (k >= s && g_entries[k] > key) { g_entries[k + 1] = g_entries[k]; k--; }
        g_entries[k + 1] = key;
    }
}

// ---------------- exp + transpose + partial row-sums (R7 version) -----------
__global__ void exp_transpose(const float* __restrict__ l0,
                              const float* __restrict__ l1,
                              const float* __restrict__ l2) {
    __shared__ float tile[32][33];
    int m  = blockIdx.z;
    int j0 = blockIdx.x * 32;
    int b0 = blockIdx.y * 32;
    const float* lg = (m == 0) ? l0 : (m == 1) ? l1 : l2;
    int tx = threadIdx.x, ty = threadIdx.y;   // (32, 8)

    float vs[4];
#pragma unroll
    for (int k = 0; k < 4; k++) {
        int bl = ty + k * 8;
        int j  = j0 + tx;
        float v = 0.f;
        if (j < VV) v = __expf(lg[(size_t)(b0 + bl) * VV + j]);
        vs[k] = v;
        tile[bl][tx] = v;
    }
#pragma unroll
    for (int k = 0; k < 4; k++) {
        float s = vs[k];
#pragma unroll
        for (int o = 16; o; o >>= 1) s += __shfl_xor_sync(0xffffffffu, s, o);
        if (tx == 0)
            g_psum[(size_t)(m * BB + b0 + ty + k * 8) * NJB + blockIdx.x] = s;
    }
    __syncthreads();
#pragma unroll
    for (int k = 0; k < 4; k++) {
        int jl = ty + k * 8;
        int j  = j0 + jl;
        if (j < VV)
            g_probsT[((size_t)m * VV + j) * BB + b0 + tx] = __float2half(tile[tx][jl]);
    }
}

// one block per (m,b) row: sum 1571 partials (coalesced), emit w_m/sum
__global__ void reduce_scale(const float* __restrict__ w) {
    int row = blockIdx.x;                 // 0 .. MM*BB-1
    int t = threadIdx.x, lane = t & 31, wp = t >> 5;
    const float* p = &g_psum[(size_t)row * NJB];
    float s = 0.f;
    for (int i = t; i < NJB; i += 256) s += p[i];
#pragma unroll
    for (int o = 16; o; o >>= 1) s += __shfl_xor_sync(0xffffffffu, s, o);
    __shared__ float ws[8];
    if (lane == 0) ws[wp] = s;
    __syncthreads();
    if (t == 0) {
        float tot = 0.f;
#pragma unroll
        for (int i = 0; i < 8; i++) tot += ws[i];
        g_scale[row] = w[row / BB] / tot;
    }
}

// ---------------- gather v5 (R9 version, unchanged) --------------------------
#define GCAP 192
__global__ void gather_union(float* __restrict__ out) {
    __shared__ float2 tile[32][129];  // [ul][b-pair], +1 pad
    __shared__ int soff[33];
    __shared__ int ent[GCAP];
    int t    = threadIdx.x;           // 256 threads
    int half = t >> 7;                // 0 or 1
    int tp   = t & 127;               // batch-pair index
    int u0 = blockIdx.x * 32;

    if (t < 33) soff[t] = g_off[u0 + t];
    float2 sc0 = *reinterpret_cast<const float2*>(&g_scale[2 * tp]);
    float2 sc1 = *reinterpret_cast<const float2*>(&g_scale[BB + 2 * tp]);
    float2 sc2 = *reinterpret_cast<const float2*>(&g_scale[2 * BB + 2 * tp]);
    __syncthreads();
    int s0 = soff[0];
    int n  = soff[32] - s0;           // total entries for this block (avg ~74)
    bool fits = (n <= GCAP);
    if (fits)
        for (int k = t; k < n; k += 256) ent[k] = g_entries[s0 + k];
    __syncthreads();

    const __half2* pt = reinterpret_cast<const __half2*>(g_probsT);

    for (int ug = half * 16; ug < half * 16 + 16; ug += 4) {
        int sA = soff[ug + 0] - s0, lA = soff[ug + 1] - soff[ug + 0];
        int sB = soff[ug + 1] - s0, lB = soff[ug + 2] - soff[ug + 1];
        int sC = soff[ug + 2] - s0, lC = soff[ug + 3] - soff[ug + 2];
        int sD = soff[ug + 3] - s0, lD = soff[ug + 4] - soff[ug + 3];
        float2 aA = {0.f, 0.f}, aB = {0.f, 0.f}, aC = {0.f, 0.f}, aD = {0.f, 0.f};
        int L = max(max(lA, lB), max(lC, lD));
        if (fits) {
            for (int i = 0; i < L; i++) {
                if (i < lA) { int p = ent[sA + i];
                    float2 s = (p >= 2 * VV) ? sc2 : (p >= VV) ? sc1 : sc0;
                    float2 v = __half22float2(pt[(size_t)p * (BB / 2) + tp]);
                    aA.x += v.x * s.x; aA.y += v.y * s.y; }
                if (i < lB) { int p = ent[sB + i];
                    float2 s = (p >= 2 * VV) ? sc2 : (p >= VV) ? sc1 : sc0;
                    float2 v = __half22float2(pt[(size_t)p * (BB / 2) + tp]);
                    aB.x += v.x * s.x; aB.y += v.y * s.y; }
                if (i < lC) { int p = ent[sC + i];
                    float2 s = (p >= 2 * VV) ? sc2 : (p >= VV) ? sc1 : sc0;
                    float2 v = __half22float2(pt[(size_t)p * (BB / 2) + tp]);
                    aC.x += v.x * s.x; aC.y += v.y * s.y; }
                if (i < lD) { int p = ent[sD + i];
                    float2 s = (p >= 2 * VV) ? sc2 : (p >= VV) ? sc1 : sc0;
                    float2 v = __half22float2(pt[(size_t)p * (BB / 2) + tp]);
                    aD.x += v.x * s.x; aD.y += v.y * s.y; }
            }
        } else {
            for (int i = 0; i < L; i++) {
                if (i < lA) { int p = g_entries[s0 + sA + i];
                    float2 s = (p >= 2 * VV) ? sc2 : (p >= VV) ? sc1 : sc0;
                    float2 v = __half22float2(pt[(size_t)p * (BB / 2) + tp]);
                    aA.x += v.x * s.x; aA.y += v.y * s.y; }
                if (i < lB) { int p = g_entries[s0 + sB + i];
                    float2 s = (p >= 2 * VV) ? sc2 : (p >= VV) ? sc1 : sc0;
                    float2 v = __half22float2(pt[(size_t)p * (BB / 2) + tp]);
                    aB.x += v.x * s.x; aB.y += v.y * s.y; }
                if (i < lC) { int p = g_entries[s0 + sC + i];
                    float2 s = (p >= 2 * VV) ? sc2 : (p >= VV) ? sc1 : sc0;
                    float2 v = __half22float2(pt[(size_t)p * (BB / 2) + tp]);
                    aC.x += v.x * s.x; aC.y += v.y * s.y; }
                if (i < lD) { int p = g_entries[s0 + sD + i];
                    float2 s = (p >= 2 * VV) ? sc2 : (p >= VV) ? sc1 : sc0;
                    float2 v = __half22float2(pt[(size_t)p * (BB / 2) + tp]);
                    aD.x += v.x * s.x; aD.y += v.y * s.y; }
            }
        }
        tile[ug + 0][tp] = aA;
        tile[ug + 1][tp] = aB;
        tile[ug + 2][tp] = aC;
        tile[ug + 3][tp] = aD;
    }
    __syncthreads();
    for (int it = 0; it < 16; it++) {
        int ul = t & 31;
        int bp = (t >> 5) + it * 8;   // batch pair 0..127
        float2 v = tile[ul][bp];
        out[(size_t)(2 * bp) * UU + u0 + ul]     = v.x;
        out[(size_t)(2 * bp + 1) * UU + u0 + ul] = v.y;
    }
}

// ---------------- launch -------------------------------------------------------
// Order chosen so exp_transpose sits at our launch index 3: ncu's fixed
// capture slot (-s 5 -c 1, with 2 harness launches ahead of ours) then
// profiles exp_transpose instead of fill_entries. Dependency-safe: exp only
// needs logits; scan precedes fill; fill/sort precede gather.
extern "C" void kernel_launch(void* const* d_in, const int* in_sizes, int n_in,
                              void* d_out, int out_size) {
    const float* l0 = (const float*)d_in[0];
    const float* l1 = (const float*)d_in[1];
    const float* l2 = (const float*)d_in[2];
    const int*   m0 = (const int*)d_in[3];
    const int*   m1 = (const int*)d_in[4];
    const int*   m2 = (const int*)d_in[5];
    const float* w  = (const float*)d_in[6];
    float* out = (float*)d_out;

    zero_counts<<<UU / 256, 256>>>();
    count_entries<<<(NE + 255) / 256, 256>>>(m0, m1, m2);
    scan_counts<<<1, 1024>>>();
    exp_transpose<<<dim3(NJB, BB / 32, MM), dim3(32, 8)>>>(l0, l1, l2);
    fill_entries<<<(NE + 255) / 256, 256>>>(m0, m1, m2);
    sort_buckets<<<UU / 256, 256>>>();
    reduce_scale<<<MM * BB, 256>>>(w);
    gather_union<<<UU / 32, 256>>>(out);
}

// round 11
// speedup vs baseline: 1.0581x; 1.0581x over previous
#include <cuda_runtime.h>
#include <cuda_fp16.h>
#include <math.h>

#define BB 256
#define VV 50257
#define UU 65536
#define MM 3
#define NE (MM * VV)        // 150771 total (model, vocab) entries
#define NJB ((VV + 31) / 32) // 1571 j-blocks per row

// ---------------- scratch (device globals; no allocation at launch time) ----
__device__ __half g_probsT[(size_t)MM * VV * BB];  // [m][j][b], b contiguous, UNNORMALIZED exp (fp16)
__device__ float g_psum[(size_t)MM * BB * NJB];    // per-(m,b) partial sums (fp32)
__device__ float g_scale[MM * BB];                 // w_m / sum
__device__ int   g_count[UU];
__device__ int   g_off[UU + 1];
__device__ int   g_cursor[UU];
__device__ int   g_entries[NE];                    // packed pidx = m*VV + j

// ---------------- CSR inverse-map build ------------------------------------
__global__ void zero_counts() {
    int i = blockIdx.x * blockDim.x + threadIdx.x;
    if (i < UU) g_count[i] = 0;
}

__global__ void count_entries(const int* __restrict__ m0,
                              const int* __restrict__ m1,
                              const int* __restrict__ m2) {
    int idx = blockIdx.x * blockDim.x + threadIdx.x;
    if (idx >= NE) return;
    int m = idx / VV;
    int j = idx - m * VV;
    const int* mp = (m == 0) ? m0 : (m == 1) ? m1 : m2;
    atomicAdd(&g_count[mp[j]], 1);
}

// coalesced exclusive scan of 65536 counts: 1 block, 32 warps, warp-chunked
__global__ void scan_counts() {
    __shared__ int warp_tot[32];
    __shared__ int warp_pre[32];
    int t = threadIdx.x, lane = t & 31, w = t >> 5;
    const int CH = UU / 32;            // 2048 elements per warp
    int base = w * CH;

    int tot = 0;
    for (int i = lane; i < CH; i += 32) tot += g_count[base + i];
#pragma unroll
    for (int o = 16; o; o >>= 1) tot += __shfl_xor_sync(0xffffffffu, tot, o);
    if (lane == 0) warp_tot[w] = tot;
    __syncthreads();

    if (w == 0) {
        int v = warp_tot[lane];
        int s = v;
#pragma unroll
        for (int o = 1; o < 32; o <<= 1) {
            int x = __shfl_up_sync(0xffffffffu, s, o);
            if (lane >= o) s += x;
        }
        warp_pre[lane] = s - v;
        if (lane == 31) g_off[UU] = s;
    }
    __syncthreads();

    int run = warp_pre[w];
    for (int i = lane; i < CH; i += 32) {
        int v = g_count[base + i];
        int s = v;
#pragma unroll
        for (int o = 1; o < 32; o <<= 1) {
            int x = __shfl_up_sync(0xffffffffu, s, o);
            if (lane >= o) s += x;
        }
        int excl = run + s - v;
        g_off[base + i]    = excl;
        g_cursor[base + i] = excl;
        run += __shfl_sync(0xffffffffu, s, 31);
    }
}

__global__ void fill_entries(const int* __restrict__ m0,
                             const int* __restrict__ m1,
                             const int* __restrict__ m2) {
    int idx = blockIdx.x * blockDim.x + threadIdx.x;
    if (idx >= NE) return;
    int m = idx / VV;
    int j = idx - m * VV;
    const int* mp = (m == 0) ? m0 : (m == 1) ? m1 : m2;
    int u = mp[j];
    int pos = atomicAdd(&g_cursor[u], 1);
    g_entries[pos] = idx;   // pidx = m*VV + j
}

// canonicalize entry order within each bucket (determinism across replays)
__global__ void sort_buckets() {
    int u = blockIdx.x * blockDim.x + threadIdx.x;
    if (u >= UU) return;
    int s = g_off[u], e = g_off[u + 1];
    for (int i = s + 1; i < e; i++) {
        int key = g_entries[i];
        int k = i - 1;
        while (k >= s && g_entries[k] > key) { g_entries[k + 1] = g_entries[k]; k--; }
        g_entries[k + 1] = key;
    }
}

// ---------------- exp + transpose v3: no shfl reduce, 32-bit indexing --------
// row sums built in the write phase: thread (tx,ty) already reads 4 j-values
// of b-row b0+tx from the tile, so the sum costs 3 FADD + 1 smem partial.
__global__ void exp_transpose(const float* __restrict__ l0,
                              const float* __restrict__ l1,
                              const float* __restrict__ l2) {
    __shared__ float tile[32][33];
    __shared__ float part[32][9];     // [b_local][warp]; stride 9 coprime 32
    int m  = blockIdx.z;
    int j0 = blockIdx.x * 32;
    int b0 = blockIdx.y * 32;
    const float* lg = (m == 0) ? l0 : (m == 1) ? l1 : l2;
    int tx = threadIdx.x, ty = threadIdx.y;   // (32, 8)

    // phase 1: load + exp (coalesced along j), stage in tile[b][j]
#pragma unroll
    for (int k = 0; k < 4; k++) {
        int bl = ty + k * 8;
        int j  = j0 + tx;
        float v = 0.f;
        if (j < VV) v = __expf(lg[(size_t)(b0 + bl) * VV + j]);
        tile[bl][tx] = v;
    }
    __syncthreads();

    // phase 2: transposed store (32-bit index) + per-thread partial row sum
    float s = 0.f;
#pragma unroll
    for (int k = 0; k < 4; k++) {
        int jl = ty + k * 8;
        int j  = j0 + jl;
        float v = tile[tx][jl];       // bank (tx+jl)%32: conflict-free
        s += v;                       // v==0 for j>=VV tail
        if (j < VV)
            g_probsT[(unsigned)((m * VV + j) * BB) + b0 + tx] = __float2half(v);
    }
    part[tx][ty] = s;
    __syncthreads();

    // phase 3: warp 0 folds the 8 warp-partials per b-row, writes psum
    if (ty == 0) {
        float tot = 0.f;
#pragma unroll
        for (int i = 0; i < 8; i++) tot += part[tx][i];
        g_psum[(size_t)(m * BB + b0 + tx) * NJB + blockIdx.x] = tot;
    }
}

// one block per (m,b) row: sum 1571 partials (coalesced), emit w_m/sum
__global__ void reduce_scale(const float* __restrict__ w) {
    int row = blockIdx.x;                 // 0 .. MM*BB-1
    int t = threadIdx.x, lane = t & 31, wp = t >> 5;
    const float* p = &g_psum[(size_t)row * NJB];
    float s = 0.f;
    for (int i = t; i < NJB; i += 256) s += p[i];
#pragma unroll
    for (int o = 16; o; o >>= 1) s += __shfl_xor_sync(0xffffffffu, s, o);
    __shared__ float ws[8];
    if (lane == 0) ws[wp] = s;
    __syncthreads();
    if (t == 0) {
        float tot = 0.f;
#pragma unroll
        for (int i = 0; i < 8; i++) tot += ws[i];
        g_scale[row] = w[row / BB] / tot;
    }
}

// ---------------- gather v5 (R9 version, unchanged) --------------------------
#define GCAP 192
__global__ void gather_union(float* __restrict__ out) {
    __shared__ float2 tile[32][129];  // [ul][b-pair], +1 pad
    __shared__ int soff[33];
    __shared__ int ent[GCAP];
    int t    = threadIdx.x;           // 256 threads
    int half = t >> 7;                // 0 or 1
    int tp   = t & 127;               // batch-pair index
    int u0 = blockIdx.x * 32;

    if (t < 33) soff[t] = g_off[u0 + t];
    float2 sc0 = *reinterpret_cast<const float2*>(&g_scale[2 * tp]);
    float2 sc1 = *reinterpret_cast<const float2*>(&g_scale[BB + 2 * tp]);
    float2 sc2 = *reinterpret_cast<const float2*>(&g_scale[2 * BB + 2 * tp]);
    __syncthreads();
    int s0 = soff[0];
    int n  = soff[32] - s0;           // total entries for this block (avg ~74)
    bool fits = (n <= GCAP);
    if (fits)
        for (int k = t; k < n; k += 256) ent[k] = g_entries[s0 + k];
    __syncthreads();

    const __half2* pt = reinterpret_cast<const __half2*>(g_probsT);

    for (int ug = half * 16; ug < half * 16 + 16; ug += 4) {
        int sA = soff[ug + 0] - s0, lA = soff[ug + 1] - soff[ug + 0];
        int sB = soff[ug + 1] - s0, lB = soff[ug + 2] - soff[ug + 1];
        int sC = soff[ug + 2] - s0, lC = soff[ug + 3] - soff[ug + 2];
        int sD = soff[ug + 3] - s0, lD = soff[ug + 4] - soff[ug + 3];
        float2 aA = {0.f, 0.f}, aB = {0.f, 0.f}, aC = {0.f, 0.f}, aD = {0.f, 0.f};
        int L = max(max(lA, lB), max(lC, lD));
        if (fits) {
            for (int i = 0; i < L; i++) {
                if (i < lA) { int p = ent[sA + i];
                    float2 s = (p >= 2 * VV) ? sc2 : (p >= VV) ? sc1 : sc0;
                    float2 v = __half22float2(pt[(size_t)p * (BB / 2) + tp]);
                    aA.x += v.x * s.x; aA.y += v.y * s.y; }
                if (i < lB) { int p = ent[sB + i];
                    float2 s = (p >= 2 * VV) ? sc2 : (p >= VV) ? sc1 : sc0;
                    float2 v = __half22float2(pt[(size_t)p * (BB / 2) + tp]);
                    aB.x += v.x * s.x; aB.y += v.y * s.y; }
                if (i < lC) { int p = ent[sC + i];
                    float2 s = (p >= 2 * VV) ? sc2 : (p >= VV) ? sc1 : sc0;
                    float2 v = __half22float2(pt[(size_t)p * (BB / 2) + tp]);
                    aC.x += v.x * s.x; aC.y += v.y * s.y; }
                if (i < lD) { int p = ent[sD + i];
                    float2 s = (p >= 2 * VV) ? sc2 : (p >= VV) ? sc1 : sc0;
                    float2 v = __half22float2(pt[(size_t)p * (BB / 2) + tp]);
                    aD.x += v.x * s.x; aD.y += v.y * s.y; }
            }
        } else {
            for (int i = 0; i < L; i++) {
                if (i < lA) { int p = g_entries[s0 + sA + i];
                    float2 s = (p >= 2 * VV) ? sc2 : (p >= VV) ? sc1 : sc0;
                    float2 v = __half22float2(pt[(size_t)p * (BB / 2) + tp]);
                    aA.x += v.x * s.x; aA.y += v.y * s.y; }
                if (i < lB) { int p = g_entries[s0 + sB + i];
                    float2 s = (p >= 2 * VV) ? sc2 : (p >= VV) ? sc1 : sc0;
                    float2 v = __half22float2(pt[(size_t)p * (BB / 2) + tp]);
                    aB.x += v.x * s.x; aB.y += v.y * s.y; }
                if (i < lC) { int p = g_entries[s0 + sC + i];
                    float2 s = (p >= 2 * VV) ? sc2 : (p >= VV) ? sc1 : sc0;
                    float2 v = __half22float2(pt[(size_t)p * (BB / 2) + tp]);
                    aC.x += v.x * s.x; aC.y += v.y * s.y; }
                if (i < lD) { int p = g_entries[s0 + sD + i];
                    float2 s = (p >= 2 * VV) ? sc2 : (p >= VV) ? sc1 : sc0;
                    float2 v = __half22float2(pt[(size_t)p * (BB / 2) + tp]);
                    aD.x += v.x * s.x; aD.y += v.y * s.y; }
            }
        }
        tile[ug + 0][tp] = aA;
        tile[ug + 1][tp] = aB;
        tile[ug + 2][tp] = aC;
        tile[ug + 3][tp] = aD;
    }
    __syncthreads();
    for (int it = 0; it < 16; it++) {
        int ul = t & 31;
        int bp = (t >> 5) + it * 8;   // batch pair 0..127
        float2 v = tile[ul][bp];
        out[(size_t)(2 * bp) * UU + u0 + ul]     = v.x;
        out[(size_t)(2 * bp + 1) * UU + u0 + ul] = v.y;
    }
}

// ---------------- launch -------------------------------------------------------
// exp_transpose kept at our launch index 3 so ncu's fixed capture slot
// profiles it (verifies this round's rewrite).
extern "C" void kernel_launch(void* const* d_in, const int* in_sizes, int n_in,
                              void* d_out, int out_size) {
    const float* l0 = (const float*)d_in[0];
    const float* l1 = (const float*)d_in[1];
    const float* l2 = (const float*)d_in[2];
    const int*   m0 = (const int*)d_in[3];
    const int*   m1 = (const int*)d_in[4];
    const int*   m2 = (const int*)d_in[5];
    const float* w  = (const float*)d_in[6];
    float* out = (float*)d_out;

    zero_counts<<<UU / 256, 256>>>();
    count_entries<<<(NE + 255) / 256, 256>>>(m0, m1, m2);
    scan_counts<<<1, 1024>>>();
    exp_transpose<<<dim3(NJB, BB / 32, MM), dim3(32, 8)>>>(l0, l1, l2);
    fill_entries<<<(NE + 255) / 256, 256>>>(m0, m1, m2);
    sort_buckets<<<UU / 256, 256>>>();
    reduce_scale<<<MM * BB, 256>>>(w);
    gather_union<<<UU / 32, 256>>>(out);
}

// round 12
// speedup vs baseline: 1.1172x; 1.0558x over previous
#include <cuda_runtime.h>
#include <cuda_fp16.h>
#include <math.h>

#define BB 256
#define VV 50257
#define UU 65536
#define MM 3
#define NE (MM * VV)        // 150771 total (model, vocab) entries
#define NJB ((VV + 31) / 32) // 1571 j-blocks per row

// ---------------- scratch (device globals; no allocation at launch time) ----
__device__ __half g_probsT[(size_t)MM * VV * BB];  // [m][j][b], b contiguous, UNNORMALIZED exp (fp16)
__device__ float g_psum[(size_t)MM * BB * NJB];    // per-(m,b) partial sums (fp32)
__device__ float g_scale[MM * BB];                 // w_m / sum
__device__ int   g_count[UU];
__device__ int   g_off[UU + 1];
__device__ int   g_cursor[UU];
__device__ int   g_entries[NE];                    // packed pidx = m*VV + j

// ---------------- CSR inverse-map build ------------------------------------
__global__ void zero_counts() {
    int i = blockIdx.x * blockDim.x + threadIdx.x;
    if (i < UU) g_count[i] = 0;
}

__global__ void count_entries(const int* __restrict__ m0,
                              const int* __restrict__ m1,
                              const int* __restrict__ m2) {
    int idx = blockIdx.x * blockDim.x + threadIdx.x;
    if (idx >= NE) return;
    int m = idx / VV;
    int j = idx - m * VV;
    const int* mp = (m == 0) ? m0 : (m == 1) ? m1 : m2;
    atomicAdd(&g_count[mp[j]], 1);
}

// coalesced exclusive scan of 65536 counts: 1 block, 32 warps, warp-chunked
__global__ void scan_counts() {
    __shared__ int warp_tot[32];
    __shared__ int warp_pre[32];
    int t = threadIdx.x, lane = t & 31, w = t >> 5;
    const int CH = UU / 32;            // 2048 elements per warp
    int base = w * CH;

    int tot = 0;
    for (int i = lane; i < CH; i += 32) tot += g_count[base + i];
#pragma unroll
    for (int o = 16; o; o >>= 1) tot += __shfl_xor_sync(0xffffffffu, tot, o);
    if (lane == 0) warp_tot[w] = tot;
    __syncthreads();

    if (w == 0) {
        int v = warp_tot[lane];
        int s = v;
#pragma unroll
        for (int o = 1; o < 32; o <<= 1) {
            int x = __shfl_up_sync(0xffffffffu, s, o);
            if (lane >= o) s += x;
        }
        warp_pre[lane] = s - v;
        if (lane == 31) g_off[UU] = s;
    }
    __syncthreads();

    int run = warp_pre[w];
    for (int i = lane; i < CH; i += 32) {
        int v = g_count[base + i];
        int s = v;
#pragma unroll
        for (int o = 1; o < 32; o <<= 1) {
            int x = __shfl_up_sync(0xffffffffu, s, o);
            if (lane >= o) s += x;
        }
        int excl = run + s - v;
        g_off[base + i]    = excl;
        g_cursor[base + i] = excl;
        run += __shfl_sync(0xffffffffu, s, 31);
    }
}

__global__ void fill_entries(const int* __restrict__ m0,
                             const int* __restrict__ m1,
                             const int* __restrict__ m2) {
    int idx = blockIdx.x * blockDim.x + threadIdx.x;
    if (idx >= NE) return;
    int m = idx / VV;
    int j = idx - m * VV;
    const int* mp = (m == 0) ? m0 : (m == 1) ? m1 : m2;
    int u = mp[j];
    int pos = atomicAdd(&g_cursor[u], 1);
    g_entries[pos] = idx;   // pidx = m*VV + j
}

// canonicalize entry order within each bucket (determinism across replays)
__global__ void sort_buckets() {
    int u = blockIdx.x * blockDim.x + threadIdx.x;
    if (u >= UU) return;
    int s = g_off[u], e = g_off[u + 1];
    for (int i = s + 1; i < e; i++) {
        int key = g_entries[i];
        int k = i - 1;
        while (k >= s && g_entries[k] > key) { g_entries[k + 1] = g_entries[k]; k--; }
        g_entries[k + 1] = key;
    }
}

// ---------------- exp + transpose v3 (R11 version, unchanged) ----------------
__global__ void exp_transpose(const float* __restrict__ l0,
                              const float* __restrict__ l1,
                              const float* __restrict__ l2) {
    __shared__ float tile[32][33];
    __shared__ float part[32][9];     // [b_local][warp]; stride 9 coprime 32
    int m  = blockIdx.z;
    int j0 = blockIdx.x * 32;
    int b0 = blockIdx.y * 32;
    const float* lg = (m == 0) ? l0 : (m == 1) ? l1 : l2;
    int tx = threadIdx.x, ty = threadIdx.y;   // (32, 8)

#pragma unroll
    for (int k = 0; k < 4; k++) {
        int bl = ty + k * 8;
        int j  = j0 + tx;
        float v = 0.f;
        if (j < VV) v = __expf(lg[(size_t)(b0 + bl) * VV + j]);
        tile[bl][tx] = v;
    }
    __syncthreads();

    float s = 0.f;
#pragma unroll
    for (int k = 0; k < 4; k++) {
        int jl = ty + k * 8;
        int j  = j0 + jl;
        float v = tile[tx][jl];       // bank (tx+jl)%32: conflict-free
        s += v;                       // v==0 for j>=VV tail
        if (j < VV)
            g_probsT[(unsigned)((m * VV + j) * BB) + b0 + tx] = __float2half(v);
    }
    part[tx][ty] = s;
    __syncthreads();

    if (ty == 0) {
        float tot = 0.f;
#pragma unroll
        for (int i = 0; i < 8; i++) tot += part[tx][i];
        g_psum[(size_t)(m * BB + b0 + tx) * NJB + blockIdx.x] = tot;
    }
}

// one block per (m,b) row: sum 1571 partials (coalesced), emit w_m/sum
__global__ void reduce_scale(const float* __restrict__ w) {
    int row = blockIdx.x;                 // 0 .. MM*BB-1
    int t = threadIdx.x, lane = t & 31, wp = t >> 5;
    const float* p = &g_psum[(size_t)row * NJB];
    float s = 0.f;
    for (int i = t; i < NJB; i += 256) s += p[i];
#pragma unroll
    for (int o = 16; o; o >>= 1) s += __shfl_xor_sync(0xffffffffu, s, o);
    __shared__ float ws[8];
    if (lane == 0) ws[wp] = s;
    __syncthreads();
    if (t == 0) {
        float tot = 0.f;
#pragma unroll
        for (int i = 0; i < 8; i++) tot += ws[i];
        g_scale[row] = w[row / BB] / tot;
    }
}

// ---------------- gather v6: 8 concurrent bucket streams per warp (MLP=8) ----
// half h (t>>7) processes u-groups [16h,16h+16) in 2 groups of 8; thread
// t&127 owns batch pair (2tp,2tp+1) via half2 loads (128B warp transactions).
// In-flight bytes/SM ~2x v5 -> crosses the BW x latency threshold for HBM.
#define GCAP 192
__global__ void gather_union(float* __restrict__ out) {
    __shared__ float2 tile[32][129];  // [ul][b-pair], +1 pad
    __shared__ int soff[33];
    __shared__ int ent[GCAP];
    int t    = threadIdx.x;           // 256 threads
    int half = t >> 7;                // 0 or 1
    int tp   = t & 127;               // batch-pair index
    int u0 = blockIdx.x * 32;

    if (t < 33) soff[t] = g_off[u0 + t];
    float2 sc0 = *reinterpret_cast<const float2*>(&g_scale[2 * tp]);
    float2 sc1 = *reinterpret_cast<const float2*>(&g_scale[BB + 2 * tp]);
    float2 sc2 = *reinterpret_cast<const float2*>(&g_scale[2 * BB + 2 * tp]);
    __syncthreads();
    int s0 = soff[0];
    int n  = soff[32] - s0;           // total entries for this block (avg ~74)
    bool fits = (n <= GCAP);
    if (fits)
        for (int k = t; k < n; k += 256) ent[k] = g_entries[s0 + k];
    __syncthreads();

    const __half2* pt = reinterpret_cast<const __half2*>(g_probsT);

    for (int ug = half * 16; ug < half * 16 + 16; ug += 8) {
        int sS[8], lS[8];
        float2 acc[8];
#pragma unroll
        for (int q = 0; q < 8; q++) {
            sS[q] = soff[ug + q] - s0;
            lS[q] = soff[ug + q + 1] - soff[ug + q];
            acc[q] = make_float2(0.f, 0.f);
        }
        int L = 0;
#pragma unroll
        for (int q = 0; q < 8; q++) L = max(L, lS[q]);

        if (fits) {
            for (int i = 0; i < L; i++) {
#pragma unroll
                for (int q = 0; q < 8; q++) {
                    if (i < lS[q]) {
                        int p = ent[sS[q] + i];
                        float2 s = (p >= 2 * VV) ? sc2 : (p >= VV) ? sc1 : sc0;
                        float2 v = __half22float2(pt[(size_t)p * (BB / 2) + tp]);
                        acc[q].x += v.x * s.x;
                        acc[q].y += v.y * s.y;
                    }
                }
            }
        } else {
            for (int i = 0; i < L; i++) {
#pragma unroll
                for (int q = 0; q < 8; q++) {
                    if (i < lS[q]) {
                        int p = g_entries[s0 + sS[q] + i];
                        float2 s = (p >= 2 * VV) ? sc2 : (p >= VV) ? sc1 : sc0;
                        float2 v = __half22float2(pt[(size_t)p * (BB / 2) + tp]);
                        acc[q].x += v.x * s.x;
                        acc[q].y += v.y * s.y;
                    }
                }
            }
        }
#pragma unroll
        for (int q = 0; q < 8; q++) tile[ug + q][tp] = acc[q];
    }
    __syncthreads();
    for (int it = 0; it < 16; it++) {
        int ul = t & 31;
        int bp = (t >> 5) + it * 8;   // batch pair 0..127
        float2 v = tile[ul][bp];
        out[(size_t)(2 * bp) * UU + u0 + ul]     = v.x;
        out[(size_t)(2 * bp + 1) * UU + u0 + ul] = v.y;
    }
}

// ---------------- launch -------------------------------------------------------
// exp_transpose kept at our launch index 3 so ncu's fixed capture slot
// profiles it (control: should stay ~57.6us; any total delta is gather).
extern "C" void kernel_launch(void* const* d_in, const int* in_sizes, int n_in,
                              void* d_out, int out_size) {
    const float* l0 = (const float*)d_in[0];
    const float* l1 = (const float*)d_in[1];
    const float* l2 = (const float*)d_in[2];
    const int*   m0 = (const int*)d_in[3];
    const int*   m1 = (const int*)d_in[4];
    const int*   m2 = (const int*)d_in[5];
    const float* w  = (const float*)d_in[6];
    float* out = (float*)d_out;

    zero_counts<<<UU / 256, 256>>>();
    count_entries<<<(NE + 255) / 256, 256>>>(m0, m1, m2);
    scan_counts<<<1, 1024>>>();
    exp_transpose<<<dim3(NJB, BB / 32, MM), dim3(32, 8)>>>(l0, l1, l2);
    fill_entries<<<(NE + 255) / 256, 256>>>(m0, m1, m2);
    sort_buckets<<<UU / 256, 256>>>();
    reduce_scale<<<MM * BB, 256>>>(w);
    gather_union<<<UU / 32, 256>>>(out);
}

// round 13
// speedup vs baseline: 1.1938x; 1.0685x over previous
#include <cuda_runtime.h>
#include <cuda_fp16.h>
#include <math.h>

#define BB 256
#define VV 50257
#define UU 65536
#define MM 3
#define NE (MM * VV)        // 150771 total (model, vocab) entries
#define NJB ((VV + 31) / 32) // 1571 j-blocks per row

// ---------------- scratch (device globals; no allocation at launch time) ----
__device__ __half g_probsT[(size_t)MM * VV * BB];  // [m][j][b], b contiguous, UNNORMALIZED exp (fp16)
__device__ float g_psum[(size_t)MM * BB * NJB];    // per-(m,b) partial sums (fp32)
__device__ float g_scale[MM * BB];                 // w_m / sum
__device__ int   g_count[UU];
__device__ int   g_off[UU + 1];
__device__ int   g_cursor[UU];
__device__ int   g_entries[NE];                    // packed pidx = m*VV + j

// ---------------- CSR inverse-map build ------------------------------------
__global__ void zero_counts() {
    int i = blockIdx.x * blockDim.x + threadIdx.x;
    if (i < UU) g_count[i] = 0;
}

__global__ void count_entries(const int* __restrict__ m0,
                              const int* __restrict__ m1,
                              const int* __restrict__ m2) {
    int idx = blockIdx.x * blockDim.x + threadIdx.x;
    if (idx >= NE) return;
    int m = idx / VV;
    int j = idx - m * VV;
    const int* mp = (m == 0) ? m0 : (m == 1) ? m1 : m2;
    atomicAdd(&g_count[mp[j]], 1);
}

// coalesced exclusive scan of 65536 counts: 1 block, 32 warps, warp-chunked
__global__ void scan_counts() {
    __shared__ int warp_tot[32];
    __shared__ int warp_pre[32];
    int t = threadIdx.x, lane = t & 31, w = t >> 5;
    const int CH = UU / 32;            // 2048 elements per warp
    int base = w * CH;

    int tot = 0;
    for (int i = lane; i < CH; i += 32) tot += g_count[base + i];
#pragma unroll
    for (int o = 16; o; o >>= 1) tot += __shfl_xor_sync(0xffffffffu, tot, o);
    if (lane == 0) warp_tot[w] = tot;
    __syncthreads();

    if (w == 0) {
        int v = warp_tot[lane];
        int s = v;
#pragma unroll
        for (int o = 1; o < 32; o <<= 1) {
            int x = __shfl_up_sync(0xffffffffu, s, o);
            if (lane >= o) s += x;
        }
        warp_pre[lane] = s - v;
        if (lane == 31) g_off[UU] = s;
    }
    __syncthreads();

    int run = warp_pre[w];
    for (int i = lane; i < CH; i += 32) {
        int v = g_count[base + i];
        int s = v;
#pragma unroll
        for (int o = 1; o < 32; o <<= 1) {
            int x = __shfl_up_sync(0xffffffffu, s, o);
            if (lane >= o) s += x;
        }
        int excl = run + s - v;
        g_off[base + i]    = excl;
        g_cursor[base + i] = excl;
        run += __shfl_sync(0xffffffffu, s, 31);
    }
}

__global__ void fill_entries(const int* __restrict__ m0,
                             const int* __restrict__ m1,
                             const int* __restrict__ m2) {
    int idx = blockIdx.x * blockDim.x + threadIdx.x;
    if (idx >= NE) return;
    int m = idx / VV;
    int j = idx - m * VV;
    const int* mp = (m == 0) ? m0 : (m == 1) ? m1 : m2;
    int u = mp[j];
    int pos = atomicAdd(&g_cursor[u], 1);
    g_entries[pos] = idx;   // pidx = m*VV + j
}

// canonicalize entry order within each bucket (determinism across replays)
__global__ void sort_buckets() {
    int u = blockIdx.x * blockDim.x + threadIdx.x;
    if (u >= UU) return;
    int s = g_off[u], e = g_off[u + 1];
    for (int i = s + 1; i < e; i++) {
        int key = g_entries[i];
        int k = i - 1;
        while (k >= s && g_entries[k] > key) { g_entries[k + 1] = g_entries[k]; k--; }
        g_entries[k + 1] = key;
    }
}

// ---------------- exp + transpose v3 (R11 version, unchanged) ----------------
__global__ void exp_transpose(const float* __restrict__ l0,
                              const float* __restrict__ l1,
                              const float* __restrict__ l2) {
    __shared__ float tile[32][33];
    __shared__ float part[32][9];     // [b_local][warp]; stride 9 coprime 32
    int m  = blockIdx.z;
    int j0 = blockIdx.x * 32;
    int b0 = blockIdx.y * 32;
    const float* lg = (m == 0) ? l0 : (m == 1) ? l1 : l2;
    int tx = threadIdx.x, ty = threadIdx.y;   // (32, 8)

#pragma unroll
    for (int k = 0; k < 4; k++) {
        int bl = ty + k * 8;
        int j  = j0 + tx;
        float v = 0.f;
        if (j < VV) v = __expf(lg[(size_t)(b0 + bl) * VV + j]);
        tile[bl][tx] = v;
    }
    __syncthreads();

    float s = 0.f;
#pragma unroll
    for (int k = 0; k < 4; k++) {
        int jl = ty + k * 8;
        int j  = j0 + jl;
        float v = tile[tx][jl];       // bank (tx+jl)%32: conflict-free
        s += v;                       // v==0 for j>=VV tail
        if (j < VV)
            g_probsT[(unsigned)((m * VV + j) * BB) + b0 + tx] = __float2half(v);
    }
    part[tx][ty] = s;
    __syncthreads();

    if (ty == 0) {
        float tot = 0.f;
#pragma unroll
        for (int i = 0; i < 8; i++) tot += part[tx][i];
        g_psum[(size_t)(m * BB + b0 + tx) * NJB + blockIdx.x] = tot;
    }
}

// one block per (m,b) row: sum 1571 partials (coalesced), emit w_m/sum
__global__ void reduce_scale(const float* __restrict__ w) {
    int row = blockIdx.x;                 // 0 .. MM*BB-1
    int t = threadIdx.x, lane = t & 31, wp = t >> 5;
    const float* p = &g_psum[(size_t)row * NJB];
    float s = 0.f;
    for (int i = t; i < NJB; i += 256) s += p[i];
#pragma unroll
    for (int o = 16; o; o >>= 1) s += __shfl_xor_sync(0xffffffffu, s, o);
    __shared__ float ws[8];
    if (lane == 0) ws[wp] = s;
    __syncthreads();
    if (t == 0) {
        float tot = 0.f;
#pragma unroll
        for (int i = 0; i < 8; i++) tot += ws[i];
        g_scale[row] = w[row / BB] / tot;
    }
}

// ---------------- gather v7: flat tagged entry list + register double-buffer -
// Each half (t>>7) runs ONE flat loop over its 16 buckets' entries; chunk c+1's
// 8 half2 loads are prefetched into registers while chunk c is accumulated into
// the smem tile (indexed RMW). Latency hides behind compute instead of
// serializing per dynamic iteration. Accumulation order per bucket unchanged.
#define GCAP 256
__global__ void __launch_bounds__(256) gather_union(float* __restrict__ out) {
    __shared__ float2 tile[32][129];          // [ul][b-pair], +1 pad
    __shared__ int soff[33];
    __shared__ int ent[GCAP + 8];
    __shared__ unsigned char eu[GCAP + 8];    // bits0-4 ul, bit6/7 model; 255=inactive
    int t    = threadIdx.x;                   // 256 threads
    int half = t >> 7;                        // 0 or 1
    int tp   = t & 127;                       // batch-pair index
    int u0 = blockIdx.x * 32;

    if (t < 33) soff[t] = g_off[u0 + t];
    float2 sc0 = *reinterpret_cast<const float2*>(&g_scale[2 * tp]);
    float2 sc1 = *reinterpret_cast<const float2*>(&g_scale[BB + 2 * tp]);
    float2 sc2 = *reinterpret_cast<const float2*>(&g_scale[2 * BB + 2 * tp]);
    // zero own half's tile rows
#pragma unroll
    for (int r = 0; r < 16; r++) tile[half * 16 + r][tp] = make_float2(0.f, 0.f);
    __syncthreads();

    int s0 = soff[0];
    int n  = soff[32] - s0;                   // total entries (avg ~74, max ~120)
    bool fits = (n <= GCAP);
    if (fits) {
        for (int k = t; k < n; k += 256) {
            int g    = s0 + k;
            int pidx = g_entries[g];
            ent[k] = pidx;
            int lo = 0, hi2 = 32;             // find ul: soff[ul] <= g < soff[ul+1]
            while (hi2 - lo > 1) { int mid = (lo + hi2) >> 1; if (soff[mid] <= g) lo = mid; else hi2 = mid; }
            int mt = (pidx >= 2 * VV) ? 128 : (pidx >= VV) ? 64 : 0;
            eu[k] = (unsigned char)(lo | mt);
        }
        for (int k = n + t; k < GCAP + 8; k += 256) { ent[k] = 0; eu[k] = 255; }
    }
    __syncthreads();

    const __half2* pt = reinterpret_cast<const __half2*>(g_probsT);
    int lo = soff[16 * half] - s0;
    int hi = soff[16 * half + 16] - s0;

    if (fits) {
        const int C = 8;
        float2 v[C]; int tg[C];
#pragma unroll
        for (int q = 0; q < C; q++) {
            int k = lo + q;
            float2 vv = make_float2(0.f, 0.f);
            int e = 255;
            if (k < hi) { e = eu[k]; vv = __half22float2(pt[(size_t)ent[k] * (BB / 2) + tp]); }
            v[q] = vv; tg[q] = e;
        }
        for (int base = lo; base < hi; base += C) {
            float2 vn[C]; int tn[C];
            int nb = base + C;
            // prefetch next chunk (independent of processing below)
#pragma unroll
            for (int q = 0; q < C; q++) {
                int k = nb + q;
                float2 vv = make_float2(0.f, 0.f);
                int e = 255;
                if (k < hi) { e = eu[k]; vv = __half22float2(pt[(size_t)ent[k] * (BB / 2) + tp]); }
                vn[q] = vv; tn[q] = e;
            }
            // process current chunk: indexed smem RMW (branchless; inactive adds 0
            // to own half's row 16h — never the other half's rows)
#pragma unroll
            for (int q = 0; q < C; q++) {
                int e = tg[q];
                float2 s = (e >= 128) ? sc2 : (e >= 64) ? sc1 : sc0;
                int ul = (e == 255) ? (half << 4) : (e & 31);
                float2* c = &tile[ul][tp];
                c->x += v[q].x * s.x;
                c->y += v[q].y * s.y;
            }
#pragma unroll
            for (int q = 0; q < C; q++) { v[q] = vn[q]; tg[q] = tn[q]; }
        }
    } else {
        // fallback (not expected for this distribution): bucket-serial, same order
        for (int ug = half * 16; ug < half * 16 + 16; ug++) {
            int bs = soff[ug], be = soff[ug + 1];
            float2 a = make_float2(0.f, 0.f);
            for (int g = bs; g < be; g++) {
                int p = g_entries[g];
                float2 s = (p >= 2 * VV) ? sc2 : (p >= VV) ? sc1 : sc0;
                float2 vv = __half22float2(pt[(size_t)p * (BB / 2) + tp]);
                a.x += vv.x * s.x;
                a.y += vv.y * s.y;
            }
            tile[ug][tp] = a;
        }
    }
    __syncthreads();
    for (int it = 0; it < 16; it++) {
        int ul = t & 31;
        int bp = (t >> 5) + it * 8;   // batch pair 0..127
        float2 v = tile[ul][bp];
        out[(size_t)(2 * bp) * UU + u0 + ul]     = v.x;
        out[(size_t)(2 * bp + 1) * UU + u0 + ul] = v.y;
    }
}

// ---------------- launch -------------------------------------------------------
// exp_transpose kept at our launch index 3 (ncu control: should stay ~59us;
// any total delta is gather).
extern "C" void kernel_launch(void* const* d_in, const int* in_sizes, int n_in,
                              void* d_out, int out_size) {
    const float* l0 = (const float*)d_in[0];
    const float* l1 = (const float*)d_in[1];
    const float* l2 = (const float*)d_in[2];
    const int*   m0 = (const int*)d_in[3];
    const int*   m1 = (const int*)d_in[4];
    const int*   m2 = (const int*)d_in[5];
    const float* w  = (const float*)d_in[6];
    float* out = (float*)d_out;

    zero_counts<<<UU / 256, 256>>>();
    count_entries<<<(NE + 255) / 256, 256>>>(m0, m1, m2);
    scan_counts<<<1, 1024>>>();
    exp_transpose<<<dim3(NJB, BB / 32, MM), dim3(32, 8)>>>(l0, l1, l2);
    fill_entries<<<(NE + 255) / 256, 256>>>(m0, m1, m2);
    sort_buckets<<<UU / 256, 256>>>();
    reduce_scale<<<MM * BB, 256>>>(w);
    gather_union<<<UU / 32, 256>>>(out);
}

// round 14
// speedup vs baseline: 1.3345x; 1.1179x over previous
#include <cuda_runtime.h>
#include <cuda_fp16.h>
#include <math.h>

#define BB 256
#define VV 50257
#define UU 65536
#define MM 3
#define NE (MM * VV)        // 150771 total (model, vocab) entries
#define NJB ((VV + 31) / 32) // 1571 j-blocks per row

// ---------------- scratch (device globals; no allocation at launch time) ----
__device__ __half g_probsT[(size_t)MM * VV * BB];  // [m][j][b], b contiguous, UNNORMALIZED exp (fp16)
__device__ float g_psum[(size_t)MM * BB * NJB];    // per-(m,b) partial sums (fp32)
__device__ float g_scale[MM * BB];                 // w_m / sum
__device__ int   g_count[UU];
__device__ int   g_off[UU + 1];
__device__ int   g_cursor[UU];
__device__ int   g_entries[NE];                    // packed pidx = m*VV + j

// ---------------- CSR inverse-map build ------------------------------------
__global__ void zero_counts() {
    int i = blockIdx.x * blockDim.x + threadIdx.x;
    if (i < UU) g_count[i] = 0;
}

__global__ void count_entries(const int* __restrict__ m0,
                              const int* __restrict__ m1,
                              const int* __restrict__ m2) {
    int idx = blockIdx.x * blockDim.x + threadIdx.x;
    if (idx >= NE) return;
    int m = idx / VV;
    int j = idx - m * VV;
    const int* mp = (m == 0) ? m0 : (m == 1) ? m1 : m2;
    atomicAdd(&g_count[mp[j]], 1);
}

// coalesced exclusive scan of 65536 counts: 1 block, 32 warps, warp-chunked
__global__ void scan_counts() {
    __shared__ int warp_tot[32];
    __shared__ int warp_pre[32];
    int t = threadIdx.x, lane = t & 31, w = t >> 5;
    const int CH = UU / 32;            // 2048 elements per warp
    int base = w * CH;

    int tot = 0;
    for (int i = lane; i < CH; i += 32) tot += g_count[base + i];
#pragma unroll
    for (int o = 16; o; o >>= 1) tot += __shfl_xor_sync(0xffffffffu, tot, o);
    if (lane == 0) warp_tot[w] = tot;
    __syncthreads();

    if (w == 0) {
        int v = warp_tot[lane];
        int s = v;
#pragma unroll
        for (int o = 1; o < 32; o <<= 1) {
            int x = __shfl_up_sync(0xffffffffu, s, o);
            if (lane >= o) s += x;
        }
        warp_pre[lane] = s - v;
        if (lane == 31) g_off[UU] = s;
    }
    __syncthreads();

    int run = warp_pre[w];
    for (int i = lane; i < CH; i += 32) {
        int v = g_count[base + i];
        int s = v;
#pragma unroll
        for (int o = 1; o < 32; o <<= 1) {
            int x = __shfl_up_sync(0xffffffffu, s, o);
            if (lane >= o) s += x;
        }
        int excl = run + s - v;
        g_off[base + i]    = excl;
        g_cursor[base + i] = excl;
        run += __shfl_sync(0xffffffffu, s, 31);
    }
}

__global__ void fill_entries(const int* __restrict__ m0,
                             const int* __restrict__ m1,
                             const int* __restrict__ m2) {
    int idx = blockIdx.x * blockDim.x + threadIdx.x;
    if (idx >= NE) return;
    int m = idx / VV;
    int j = idx - m * VV;
    const int* mp = (m == 0) ? m0 : (m == 1) ? m1 : m2;
    int u = mp[j];
    int pos = atomicAdd(&g_cursor[u], 1);
    g_entries[pos] = idx;   // pidx = m*VV + j
}

// canonicalize entry order within each bucket (determinism across replays)
__global__ void sort_buckets() {
    int u = blockIdx.x * blockDim.x + threadIdx.x;
    if (u >= UU) return;
    int s = g_off[u], e = g_off[u + 1];
    for (int i = s + 1; i < e; i++) {
        int key = g_entries[i];
        int k = i - 1;
        while (k >= s && g_entries[k] > key) { g_entries[k + 1] = g_entries[k]; k--; }
        g_entries[k + 1] = key;
    }
}

// ---------------- exp + transpose v4: b-tile 64, half2 (128B) stores ---------
// smem holds half-packed [j][b] tile; write phase reads a b-pair (LDS.32,
// conflict-free) and emits ONE half2 store per 2 elements: store instruction
// count and address ALU halve vs v3. Row sums: float2 partials per thread.
__global__ void exp_transpose(const float* __restrict__ l0,
                              const float* __restrict__ l1,
                              const float* __restrict__ l2) {
    __shared__ __half tileh[32][66];  // [j_local][b_local], stride 66 halves (33 words)
    __shared__ float partx[32][9];    // [tx][warp] partial for b=2tx   (9 coprime 32)
    __shared__ float party[32][9];    // [tx][warp] partial for b=2tx+1
    int m  = blockIdx.z;
    int j0 = blockIdx.x * 32;
    int b0 = blockIdx.y * 64;
    const float* lg = (m == 0) ? l0 : (m == 1) ? l1 : l2;
    int tx = threadIdx.x, ty = threadIdx.y;   // (32, 8)

    // phase 1: 64 b-rows x 32 j; coalesced loads along j; STS.16 bank=tx
#pragma unroll
    for (int k = 0; k < 8; k++) {
        int bl = ty + k * 8;
        int j  = j0 + tx;
        float v = 0.f;
        if (j < VV) v = __expf(lg[(size_t)(b0 + bl) * VV + j]);
        tileh[tx][bl] = __float2half(v);
    }
    __syncthreads();

    // phase 2: thread owns b-pair (2tx, 2tx+1); 4 j's; half2 stores (128B/warp)
    float sx = 0.f, sy = 0.f;
#pragma unroll
    for (int k = 0; k < 4; k++) {
        int jl = ty + k * 8;
        int j  = j0 + jl;
        __half2 h = *reinterpret_cast<__half2*>(&tileh[jl][2 * tx]);  // bank (33jl+tx)
        float2 f = __half22float2(h);
        sx += f.x; sy += f.y;             // zeros for j>=VV tail
        if (j < VV)
            *reinterpret_cast<__half2*>(
                &g_probsT[(unsigned)((m * VV + j) * BB) + b0 + 2 * tx]) = h;
    }
    partx[tx][ty] = sx;
    party[tx][ty] = sy;
    __syncthreads();

    // phase 3: warp 0 folds 8 warp-partials for its 2 b-rows, writes psum
    if (ty == 0) {
        float tx2 = 0.f, ty2 = 0.f;
#pragma unroll
        for (int i = 0; i < 8; i++) { tx2 += partx[tx][i]; ty2 += party[tx][i]; }
        g_psum[(size_t)(m * BB + b0 + 2 * tx) * NJB + blockIdx.x]     = tx2;
        g_psum[(size_t)(m * BB + b0 + 2 * tx + 1) * NJB + blockIdx.x] = ty2;
    }
}

// one block per (m,b) row: sum 1571 partials (coalesced), emit w_m/sum
__global__ void reduce_scale(const float* __restrict__ w) {
    int row = blockIdx.x;                 // 0 .. MM*BB-1
    int t = threadIdx.x, lane = t & 31, wp = t >> 5;
    const float* p = &g_psum[(size_t)row * NJB];
    float s = 0.f;
    for (int i = t; i < NJB; i += 256) s += p[i];
#pragma unroll
    for (int o = 16; o; o >>= 1) s += __shfl_xor_sync(0xffffffffu, s, o);
    __shared__ float ws[8];
    if (lane == 0) ws[wp] = s;
    __syncthreads();
    if (t == 0) {
        float tot = 0.f;
#pragma unroll
        for (int i = 0; i < 8; i++) tot += ws[i];
        g_scale[row] = w[row / BB] / tot;
    }
}

// ---------------- gather v7 (R13 version, unchanged) -------------------------
#define GCAP 256
__global__ void __launch_bounds__(256) gather_union(float* __restrict__ out) {
    __shared__ float2 tile[32][129];          // [ul][b-pair], +1 pad
    __shared__ int soff[33];
    __shared__ int ent[GCAP + 8];
    __shared__ unsigned char eu[GCAP + 8];    // bits0-4 ul, bit6/7 model; 255=inactive
    int t    = threadIdx.x;                   // 256 threads
    int half = t >> 7;                        // 0 or 1
    int tp   = t & 127;                       // batch-pair index
    int u0 = blockIdx.x * 32;

    if (t < 33) soff[t] = g_off[u0 + t];
    float2 sc0 = *reinterpret_cast<const float2*>(&g_scale[2 * tp]);
    float2 sc1 = *reinterpret_cast<const float2*>(&g_scale[BB + 2 * tp]);
    float2 sc2 = *reinterpret_cast<const float2*>(&g_scale[2 * BB + 2 * tp]);
#pragma unroll
    for (int r = 0; r < 16; r++) tile[half * 16 + r][tp] = make_float2(0.f, 0.f);
    __syncthreads();

    int s0 = soff[0];
    int n  = soff[32] - s0;                   // total entries (avg ~74)
    bool fits = (n <= GCAP);
    if (fits) {
        for (int k = t; k < n; k += 256) {
            int g    = s0 + k;
            int pidx = g_entries[g];
            ent[k] = pidx;
            int lo = 0, hi2 = 32;
            while (hi2 - lo > 1) { int mid = (lo + hi2) >> 1; if (soff[mid] <= g) lo = mid; else hi2 = mid; }
            int mt = (pidx >= 2 * VV) ? 128 : (pidx >= VV) ? 64 : 0;
            eu[k] = (unsigned char)(lo | mt);
        }
        for (int k = n + t; k < GCAP + 8; k += 256) { ent[k] = 0; eu[k] = 255; }
    }
    __syncthreads();

    const __half2* pt = reinterpret_cast<const __half2*>(g_probsT);
    int lo = soff[16 * half] - s0;
    int hi = soff[16 * half + 16] - s0;

    if (fits) {
        const int C = 8;
        float2 v[C]; int tg[C];
#pragma unroll
        for (int q = 0; q < C; q++) {
            int k = lo + q;
            float2 vv = make_float2(0.f, 0.f);
            int e = 255;
            if (k < hi) { e = eu[k]; vv = __half22float2(pt[(size_t)ent[k] * (BB / 2) + tp]); }
            v[q] = vv; tg[q] = e;
        }
        for (int base = lo; base < hi; base += C) {
            float2 vn[C]; int tn[C];
            int nb = base + C;
#pragma unroll
            for (int q = 0; q < C; q++) {
                int k = nb + q;
                float2 vv = make_float2(0.f, 0.f);
                int e = 255;
                if (k < hi) { e = eu[k]; vv = __half22float2(pt[(size_t)ent[k] * (BB / 2) + tp]); }
                vn[q] = vv; tn[q] = e;
            }
#pragma unroll
            for (int q = 0; q < C; q++) {
                int e = tg[q];
                float2 s = (e >= 128) ? sc2 : (e >= 64) ? sc1 : sc0;
                int ul = (e == 255) ? (half << 4) : (e & 31);
                float2* c = &tile[ul][tp];
                c->x += v[q].x * s.x;
                c->y += v[q].y * s.y;
            }
#pragma unroll
            for (int q = 0; q < C; q++) { v[q] = vn[q]; tg[q] = tn[q]; }
        }
    } else {
        for (int ug = half * 16; ug < half * 16 + 16; ug++) {
            int bs = soff[ug], be = soff[ug + 1];
            float2 a = make_float2(0.f, 0.f);
            for (int g = bs; g < be; g++) {
                int p = g_entries[g];
                float2 s = (p >= 2 * VV) ? sc2 : (p >= VV) ? sc1 : sc0;
                float2 vv = __half22float2(pt[(size_t)p * (BB / 2) + tp]);
                a.x += vv.x * s.x;
                a.y += vv.y * s.y;
            }
            tile[ug][tp] = a;
        }
    }
    __syncthreads();
    for (int it = 0; it < 16; it++) {
        int ul = t & 31;
        int bp = (t >> 5) + it * 8;   // batch pair 0..127
        float2 v = tile[ul][bp];
        out[(size_t)(2 * bp) * UU + u0 + ul]     = v.x;
        out[(size_t)(2 * bp + 1) * UU + u0 + ul] = v.y;
    }
}

// ---------------- launch -------------------------------------------------------
// exp_transpose kept at our launch index 3 (ncu verifies this round's rewrite).
extern "C" void kernel_launch(void* const* d_in, const int* in_sizes, int n_in,
                              void* d_out, int out_size) {
    const float* l0 = (const float*)d_in[0];
    const float* l1 = (const float*)d_in[1];
    const float* l2 = (const float*)d_in[2];
    const int*   m0 = (const int*)d_in[3];
    const int*   m1 = (const int*)d_in[4];
    const int*   m2 = (const int*)d_in[5];
    const float* w  = (const float*)d_in[6];
    float* out = (float*)d_out;

    zero_counts<<<UU / 256, 256>>>();
    count_entries<<<(NE + 255) / 256, 256>>>(m0, m1, m2);
    scan_counts<<<1, 1024>>>();
    exp_transpose<<<dim3(NJB, BB / 64, MM), dim3(32, 8)>>>(l0, l1, l2);
    fill_entries<<<(NE + 255) / 256, 256>>>(m0, m1, m2);
    sort_buckets<<<UU / 256, 256>>>();
    reduce_scale<<<MM * BB, 256>>>(w);
    gather_union<<<UU / 32, 256>>>(out);
}